// round 16
// baseline (speedup 1.0000x reference)
#include <cuda_runtime.h>

#define N3 9604
#define N4 2401
#define N5 625
#define NA 37890            // (N3+N4+N5)*3
#define NGT 64
#define LANES 4             // threads cooperating per anchor
#define SCALE_CLAMP 3.3322045101752038f   // log(224/8), double-rounded
#define NEGBIG 1.0e8f

// Anchor (w,h) per [level*3 + aspect_ratio_index], computed in double on host:
// area = (4*stride)^2; w = sqrt(area/ar); h = area/w;  ar in {0.5, 1.0, 2.0}
__constant__ float c_w[9] = {
    45.254833995939045f,  32.0f,  22.627416997969522f,   // p3 (stride 8)
    90.50966799187809f,   64.0f,  45.254833995939045f,   // p4 (stride 16)
    181.01933598375618f, 128.0f,  90.50966799187809f     // p5 (stride 32)
};
__constant__ float c_h[9] = {
    22.627416997969522f,  32.0f,  45.254833995939045f,
    45.254833995939045f,  64.0f,  90.50966799187809f,
    90.50966799187809f,  128.0f, 181.01933598375618f
};

__global__ __launch_bounds__(256)
void rpn_fused_kernel(const float* __restrict__ loc3,
                      const float* __restrict__ loc4,
                      const float* __restrict__ loc5,
                      const float* __restrict__ deltas,
                      const float* __restrict__ gt,
                      float* __restrict__ out)
{
    __shared__ float4 s_box[NGT];   // gt box coords
    __shared__ float  s_area[NGT];  // gt areas
    __shared__ float  s_cls[NGT];   // gt class

    const int tid = threadIdx.x;
    if (tid < NGT) {
        const float g0 = gt[tid * 5 + 0];
        const float g1 = gt[tid * 5 + 1];
        const float g2 = gt[tid * 5 + 2];
        const float g3 = gt[tid * 5 + 3];
        s_box[tid]  = make_float4(g0, g1, g2, g3);
        s_cls[tid]  = gt[tid * 5 + 4];
        s_area[tid] = (g2 - g0) * (g3 - g1);
    }
    __syncthreads();

    const int gid   = blockIdx.x * blockDim.x + tid;
    const int a_raw = gid >> 2;          // anchor id
    const int sub   = gid & 3;           // lane within group of 4
    const bool valid = (a_raw < NA);
    const int a = valid ? a_raw : 0;     // clamp: no thread exits before shfl

    // ---- which level / location / aspect ratio ----
    int li, r = a;
    const float* loc;
    if (a < 3 * N3)             { li = 0; loc = loc3; }
    else if (a < 3 * (N3 + N4)) { li = 1; loc = loc4; r = a - 3 * N3; }
    else                        { li = 2; loc = loc5; r = a - 3 * (N3 + N4); }
    const int locidx = r / 3;
    const int ar     = r - locidx * 3;

    const float xc = __ldg(&loc[2 * locidx + 0]);
    const float yc = __ldg(&loc[2 * locidx + 1]);
    const float w  = c_w[li * 3 + ar];
    const float h  = c_h[li * 3 + ar];

    // anchor box (matches reference rounding: xc - w/2 etc., all f32)
    const float ax0 = xc - 0.5f * w;
    const float ay0 = yc - 0.5f * h;
    const float ax1 = xc + 0.5f * w;
    const float ay1 = yc + 0.5f * h;

    // recompute wa/ha from the box like the reference does (f32 rounding parity)
    const float wa = ax1 - ax0;
    const float ha = ay1 - ay0;
    const float xa = ax0 + wa * 0.5f;
    const float ya = ay0 + ha * 0.5f;

    // ---- lane 0: apply deltas -> proposals (independent; overlaps IoU loop) ----
    if (sub == 0 && valid) {
        const float4 d  = reinterpret_cast<const float4*>(deltas)[a];
        const float dw  = fminf(d.z, SCALE_CLAMP);
        const float dh  = fminf(d.w, SCALE_CLAMP);
        const float xp  = d.x * wa + xa;
        const float yp  = d.y * ha + ya;
        const float wp  = expf(dw) * wa;
        const float hp  = expf(dh) * ha;
        float4 prop;
        prop.x = xp - 0.5f * wp;
        prop.y = yp - 0.5f * hp;
        prop.z = xp + 0.5f * wp;
        prop.w = yp + 0.5f * hp;
        reinterpret_cast<float4*>(out)[a] = prop;  // out base 16B-aligned
    }

    // ---- IoU argmax, branchless, cross-multiplied, S-form.
    //
    // iou = in/(S - in) with S = RN(aarea + area_g). For positives,
    // in_c/(S_c-in_c) > bin/(S_b-bin)  ⟺  in_c*S_b > bin*S_c (exact algebra),
    // so the loop never computes unions or divides. Zero-intersection
    // candidates can never win (0 > bin*S is false), so an all-zero row
    // yields (bidx=0, quality 0) == jnp.argmax. Final quality is
    // RN(bin / RN(bS - bin)) — bit-identical to the reference's quotient.
    //
    // TWO independent chains (A: g=sub+8i, B: g=sub+4+8i) halve the carried
    // FMUL->FSETP->FSEL latency; merged exactly afterwards (tie -> smaller
    // index preserves first-occurrence argmax). ----
    const float aarea = wa * ha;
    float binA = 0.0f, bSA = 1.0f;  int idxA = 0;
    float binB = 0.0f, bSB = 1.0f;  int idxB = 0;
    #pragma unroll
    for (int i = 0; i < 8; ++i) {
        const int gA = sub + (i << 3);
        const int gB = gA + 4;
        const float4 bA = s_box[gA];
        const float4 bB = s_box[gB];
        const float aA = s_area[gA];
        const float aB = s_area[gB];

        const float iwA = fmaxf(fminf(ax1, bA.z) - fmaxf(ax0, bA.x), 0.0f);
        const float ihA = fmaxf(fminf(ay1, bA.w) - fmaxf(ay0, bA.y), 0.0f);
        const float iwB = fmaxf(fminf(ax1, bB.z) - fmaxf(ax0, bB.x), 0.0f);
        const float ihB = fmaxf(fminf(ay1, bB.w) - fmaxf(ay0, bB.y), 0.0f);
        const float inA = iwA * ihA;
        const float inB = iwB * ihB;
        const float SA  = aarea + aA;
        const float SB  = aarea + aB;

        const bool uA = (inA * bSA) > (binA * SA);
        binA = uA ? inA : binA;
        bSA  = uA ? SA  : bSA;
        idxA = uA ? gA  : idxA;

        const bool uB = (inB * bSB) > (binB * SB);
        binB = uB ? inB : binB;
        bSB  = uB ? SB  : bSB;
        idxB = uB ? gB  : idxB;
    }

    // merge chains (indices interleave; tie -> smaller index)
    float bin = binA, bS = bSA;  int bidx = idxA;
    {
        const float cB = binB * bSA;
        const float cA = binA * bSB;
        const bool takeB = (cB > cA) || ((cB == cA) && (idxB < idxA));
        bin  = takeB ? binB : bin;
        bS   = takeB ? bSB  : bS;
        bidx = takeB ? idxB : bidx;
    }

    // ---- 4-lane argmax reduction (cross-mult compare; ties -> smaller g) ----
    #pragma unroll
    for (int off = 1; off < LANES; off <<= 1) {
        const float o_in = __shfl_xor_sync(0xffffffffu, bin,  off);
        const float o_S  = __shfl_xor_sync(0xffffffffu, bS,   off);
        const int   o_ix = __shfl_xor_sync(0xffffffffu, bidx, off);
        const float c = o_in * bS;
        const float d = bin  * o_S;
        const bool take = (c > d) || ((c == d) && (o_ix < bidx));
        bin  = take ? o_in : bin;
        bS   = take ? o_S  : bS;
        bidx = take ? o_ix : bidx;
    }

    // ---- single exact division: the reference's rounded quality ----
    const float best = bin / (bS - bin);   // bS-bin == RN(union) as in reference

    // ---- matched_gt (branch-free selects; all lanes compute) ----
    const bool low     = (best <= 0.3f);
    const bool neutral = !low && (best < 0.6f);
    const float4 mb = s_box[bidx];
    const float  mc = s_cls[bidx];
    const float m0 = low ? -1.0f : (neutral ? -NEGBIG : mb.x);
    const float m1 = low ? -1.0f : (neutral ? -NEGBIG : mb.y);
    const float m2 = low ? -1.0f : (neutral ? -NEGBIG : mb.z);
    const float m3 = low ? -1.0f : (neutral ? -NEGBIG : mb.w);
    const float m4 = low ? -1.0f : (neutral ? -NEGBIG : mc);

    if (valid) {
        float* om = out + (size_t)NA * 4 + (size_t)a * 5;
        const float mv = (sub == 0) ? m0 : (sub == 1) ? m1 : (sub == 2) ? m2 : m3;
        om[sub] = mv;
        if (sub == 0) om[4] = m4;
    }

    // ---- gt_deltas: lane 1 computes+stores (gd0,gd1), lane 2 (gd2,gd3).
    // Lane-selected numerators share the wa/ha denominators, so the warp
    // stream contains only TWO divisions and TWO logf sequences. logf of a
    // lane-1 (possibly negative) quotient is computed but selected away. ----
    if (valid && (sub == 1 || sub == 2)) {
        float r0, r1;
        if (m0 < 0.0f) {
            r0 = r1 = -NEGBIG;
        } else {
            const float wg = fmaxf(m2 - m0, 1.0f);
            const float hg = fmaxf(m3 - m1, 1.0f);
            const float xg = m0 + wg * 0.5f;
            const float yg = m1 + hg * 0.5f;
            const float n0 = (sub == 1) ? (xg - xa) : wg;
            const float n1 = (sub == 1) ? (yg - ya) : hg;
            const float q0 = n0 / wa;
            const float q1 = n1 / ha;
            r0 = (sub == 2) ? logf(q0) : q0;
            r1 = (sub == 2) ? logf(q1) : q1;
        }
        // gt_deltas section starts at element NA*9 = 341010 -> byte offset
        // ≡ 8 (mod 16): only 8B-aligned, so float2 stores.
        float* og = out + (size_t)NA * 9 + (size_t)a * 4;
        reinterpret_cast<float2*>(og)[sub - 1] = make_float2(r0, r1);
    }
}

extern "C" void kernel_launch(void* const* d_in, const int* in_sizes, int n_in,
                              void* d_out, int out_size)
{
    const float* loc3   = (const float*)d_in[0];
    const float* loc4   = (const float*)d_in[1];
    const float* loc5   = (const float*)d_in[2];
    const float* deltas = (const float*)d_in[3];
    const float* gt     = (const float*)d_in[4];
    float* out = (float*)d_out;

    const int threads = 256;
    const int blocks  = (NA * LANES + threads - 1) / threads;  // 593
    rpn_fused_kernel<<<blocks, threads>>>(loc3, loc4, loc5, deltas, gt, out);
}